// round 1
// baseline (speedup 1.0000x reference)
#include <cuda_runtime.h>

// Problem constants
#define B_   16
#define T_   128
#define H_   512
#define L_   2
#define V_   32000
#define M_   (B_ * T_)     // 2048 rows = flattened (b, t)
#define G4_  (4 * H_)      // 2048 gate width

// Scratch (static device globals — no runtime allocation)
__device__ float g_X0[M_ * H_];     // layer activations ping
__device__ float g_X1[M_ * H_];     // layer activations pong
__device__ float g_G [M_ * G4_];    // gate pre-activations
__device__ float g_hb[B_ * G4_];    // per-batch recurrent contribution
__device__ float g_dummy[2 * L_ * B_ * H_]; // fallback sink if out_size is logits-only

__device__ __forceinline__ float sigf(float x) { return 1.0f / (1.0f + expf(-x)); }

// ---------------------------------------------------------------------------
// Kernel 1: x = relu(embedding[tokens]); tokens = [BOS, target[:, :-1]]
// One float4 per thread over [M_, H_/4]
// ---------------------------------------------------------------------------
__global__ void embed_relu_kernel(const int* __restrict__ tgt,
                                  const float* __restrict__ emb) {
    int idx = blockIdx.x * 256 + threadIdx.x;   // 0 .. M_*128
    int m  = idx >> 7;          // H_/4 = 128 float4 per row
    int h4 = idx & 127;
    int b = m >> 7;             // T_ = 128
    int t = m & 127;
    int tok = (t == 0) ? 1 : tgt[b * T_ + t - 1];   // BOS_IDX = 1
    float4 v = reinterpret_cast<const float4*>(emb + (size_t)tok * H_)[h4];
    v.x = fmaxf(v.x, 0.f); v.y = fmaxf(v.y, 0.f);
    v.z = fmaxf(v.z, 0.f); v.w = fmaxf(v.w, 0.f);
    reinterpret_cast<float4*>(g_X0)[idx] = v;
}

// ---------------------------------------------------------------------------
// Kernel 2: hb[b][g] = dot(h0[b,:], W_hh[g,:]) + b_ih[g] + b_hh[g]
// One warp per (b, g). block = (32, 8), grid = (G4_/8, B_)
// ---------------------------------------------------------------------------
__global__ void hb_kernel(const float* __restrict__ h0,
                          const float* __restrict__ Whh,
                          const float* __restrict__ bih,
                          const float* __restrict__ bhh) {
    int g = blockIdx.x * 8 + threadIdx.y;
    int b = blockIdx.y;
    const float4* hr = reinterpret_cast<const float4*>(h0 + (size_t)b * H_);
    const float4* wr = reinterpret_cast<const float4*>(Whh + (size_t)g * H_);
    float s = 0.f;
    for (int k = threadIdx.x; k < H_ / 4; k += 32) {
        float4 a = hr[k], w = wr[k];
        s += a.x * w.x + a.y * w.y + a.z * w.z + a.w * w.w;
    }
    #pragma unroll
    for (int o = 16; o; o >>= 1) s += __shfl_xor_sync(0xffffffffu, s, o);
    if (threadIdx.x == 0) g_hb[b * G4_ + g] = s + bih[g] + bhh[g];
}

// ---------------------------------------------------------------------------
// Kernel 3: C[M,N] = A[M,K] * B[N,K]^T (+ colb[n])
// Classic 128x128x16 tiled SGEMM, 256 threads, 8x8 per-thread fragment.
// Requires M%128==0, N%128==0, K%16==0 (true for all uses here).
// ---------------------------------------------------------------------------
__global__ __launch_bounds__(256, 2)
void sgemm_nt(const float* __restrict__ A, const float* __restrict__ Bm,
              float* __restrict__ C, int N, int K,
              const float* __restrict__ colb) {
    __shared__ float As[16][128];
    __shared__ float Bs[16][128];

    const int tid = threadIdx.x;
    const int tx = tid & 15;        // N-dim thread coord (0..15)
    const int ty = tid >> 4;        // M-dim thread coord (0..15)
    const int m0 = blockIdx.y * 128;
    const int n0 = blockIdx.x * 128;

    const int lr = tid >> 2;            // 0..63 (row within half-tile)
    const int lk = (tid & 3) << 2;      // 0,4,8,12 (k offset)
    const float* Ap = A  + (size_t)(m0 + lr) * K + lk;
    const float* Bp = Bm + (size_t)(n0 + lr) * K + lk;

    float acc[8][8];
    #pragma unroll
    for (int i = 0; i < 8; ++i)
        #pragma unroll
        for (int j = 0; j < 8; ++j) acc[i][j] = 0.f;

    for (int k0 = 0; k0 < K; k0 += 16) {
        float4 a0 = *reinterpret_cast<const float4*>(Ap + k0);
        float4 a1 = *reinterpret_cast<const float4*>(Ap + (size_t)64 * K + k0);
        float4 b0 = *reinterpret_cast<const float4*>(Bp + k0);
        float4 b1 = *reinterpret_cast<const float4*>(Bp + (size_t)64 * K + k0);
        __syncthreads();
        As[lk + 0][lr]      = a0.x; As[lk + 1][lr]      = a0.y;
        As[lk + 2][lr]      = a0.z; As[lk + 3][lr]      = a0.w;
        As[lk + 0][lr + 64] = a1.x; As[lk + 1][lr + 64] = a1.y;
        As[lk + 2][lr + 64] = a1.z; As[lk + 3][lr + 64] = a1.w;
        Bs[lk + 0][lr]      = b0.x; Bs[lk + 1][lr]      = b0.y;
        Bs[lk + 2][lr]      = b0.z; Bs[lk + 3][lr]      = b0.w;
        Bs[lk + 0][lr + 64] = b1.x; Bs[lk + 1][lr + 64] = b1.y;
        Bs[lk + 2][lr + 64] = b1.z; Bs[lk + 3][lr + 64] = b1.w;
        __syncthreads();

        #pragma unroll
        for (int kk = 0; kk < 16; ++kk) {
            float4 av0 = *reinterpret_cast<const float4*>(&As[kk][ty * 8]);
            float4 av1 = *reinterpret_cast<const float4*>(&As[kk][ty * 8 + 4]);
            float4 bv0 = *reinterpret_cast<const float4*>(&Bs[kk][tx * 8]);
            float4 bv1 = *reinterpret_cast<const float4*>(&Bs[kk][tx * 8 + 4]);
            float a[8] = {av0.x, av0.y, av0.z, av0.w, av1.x, av1.y, av1.z, av1.w};
            float bb[8] = {bv0.x, bv0.y, bv0.z, bv0.w, bv1.x, bv1.y, bv1.z, bv1.w};
            #pragma unroll
            for (int i = 0; i < 8; ++i)
                #pragma unroll
                for (int j = 0; j < 8; ++j)
                    acc[i][j] = fmaf(a[i], bb[j], acc[i][j]);
        }
    }

    float cb[8];
    #pragma unroll
    for (int j = 0; j < 8; ++j)
        cb[j] = colb ? colb[n0 + tx * 8 + j] : 0.f;

    #pragma unroll
    for (int i = 0; i < 8; ++i) {
        int m = m0 + ty * 8 + i;
        float* crow = C + (size_t)m * N + n0 + tx * 8;
        #pragma unroll
        for (int j = 0; j < 8; ++j) crow[j] = acc[i][j] + cb[j];
    }
}

// ---------------------------------------------------------------------------
// Kernel 4: elementwise LSTM cell on gate pre-activations
// i,f,g,o order (torch). c = sig(f)*c0 + sig(i)*tanh(g); h = sig(o)*tanh(c)
// ---------------------------------------------------------------------------
__global__ void lstm_elem_kernel(const float* __restrict__ c0,
                                 float* __restrict__ Xn,
                                 float* __restrict__ out_h,
                                 float* __restrict__ out_c) {
    int idx = blockIdx.x * 256 + threadIdx.x;  // over M_*H_
    int m = idx >> 9;          // H_ = 512
    int j = idx & 511;
    int b = m >> 7;            // T_ = 128
    int t = m & 127;
    const float* gr  = g_G  + (size_t)m * G4_;
    const float* hbb = g_hb + (size_t)b * G4_;
    float iv = gr[j]          + hbb[j];
    float fv = gr[H_ + j]     + hbb[H_ + j];
    float gv = gr[2 * H_ + j] + hbb[2 * H_ + j];
    float ov = gr[3 * H_ + j] + hbb[3 * H_ + j];
    float c = sigf(fv) * c0[(size_t)b * H_ + j] + sigf(iv) * tanhf(gv);
    float h = sigf(ov) * tanhf(c);
    Xn[idx] = h;
    if (t == T_ - 1) {
        out_h[(size_t)b * H_ + j] = h;
        out_c[(size_t)b * H_ + j] = c;
    }
}

// ---------------------------------------------------------------------------
extern "C" void kernel_launch(void* const* d_in, const int* in_sizes, int n_in,
                              void* d_out, int out_size) {
    const float* enc_h  = (const float*)d_in[1];
    const float* enc_c  = (const float*)d_in[2];
    const int*   tgt    = (const int*)  d_in[3];
    const float* emb    = (const float*)d_in[4];
    const float* W_ih   = (const float*)d_in[5];
    const float* W_hh   = (const float*)d_in[6];
    const float* b_ih   = (const float*)d_in[7];
    const float* b_hh   = (const float*)d_in[8];
    const float* W_out  = (const float*)d_in[9];
    const float* b_out  = (const float*)d_in[10];
    float* out = (float*)d_out;

    // Resolve scratch symbol addresses once (no allocation; cached statically
    // so the captured graph contains pure kernel launches only).
    static float *X0 = nullptr, *X1 = nullptr, *Gp = nullptr, *dummy = nullptr;
    if (!X0) {
        void* p;
        cudaGetSymbolAddress(&p, g_X0);    X0    = (float*)p;
        cudaGetSymbolAddress(&p, g_X1);    X1    = (float*)p;
        cudaGetSymbolAddress(&p, g_G);     Gp    = (float*)p;
        cudaGetSymbolAddress(&p, g_dummy); dummy = (float*)p;
    }

    // Output layout per pytree flatten: [logits (M_*V_), h_last (L,B,H), c_last (L,B,H)]
    const long long need = (long long)M_ * V_ + 2LL * L_ * B_ * H_;
    float* hl;
    float* cl;
    if ((long long)out_size >= need) {
        hl = out + (size_t)M_ * V_;
        cl = hl + (size_t)L_ * B_ * H_;
    } else {
        hl = dummy;
        cl = dummy + (size_t)L_ * B_ * H_;
    }

    // 1. Embedding + ReLU
    embed_relu_kernel<<<(M_ * (H_ / 4)) / 256, 256>>>(tgt, emb);

    // 2. Two independent single-step LSTM layers (vectorized over T)
    const float* Xin = X0;
    float* Xout = X1;
    for (int l = 0; l < L_; ++l) {
        hb_kernel<<<dim3(G4_ / 8, B_), dim3(32, 8)>>>(
            enc_h + (size_t)l * B_ * H_,
            W_hh  + (size_t)l * G4_ * H_,
            b_ih  + (size_t)l * G4_,
            b_hh  + (size_t)l * G4_);
        sgemm_nt<<<dim3(G4_ / 128, M_ / 128), 256>>>(
            Xin, W_ih + (size_t)l * G4_ * H_, Gp, G4_, H_, nullptr);
        lstm_elem_kernel<<<(M_ * H_) / 256, 256>>>(
            enc_c + (size_t)l * B_ * H_, Xout,
            hl + (size_t)l * B_ * H_, cl + (size_t)l * B_ * H_);
        const float* t2 = Xout; Xout = (float*)Xin; Xin = t2;
    }

    // 3. Output projection: logits = X2 * W_out^T + b_out  (M=2048, N=32000, K=512)
    sgemm_nt<<<dim3(V_ / 128, M_ / 128), 256>>>(Xin, W_out, out, V_, H_, b_out);
}

// round 3
// speedup vs baseline: 2.5014x; 2.5014x over previous
#include <cuda_runtime.h>
#include <cuda_bf16.h>
#include <cuda.h>
#include <cstdint>

// ---------------- problem constants ----------------
#define B_    16
#define T_    128
#define H_    512
#define L_    2
#define V_    32000
#define M_    (B_ * T_)        // 2048
#define G4_   (4 * H_)         // 2048
#define KS_   (3 * H_)         // 1536 split-K  [hi|hi|lo] x [hi|lo|hi]

// ---------------- GEMM tiling ----------------
#define BM_   128
#define BN_   256
#define BK_   64               // bf16 = 128 bytes/row = SW128 atom
#define KT_   (KS_ / BK_)      // 24 k-tiles
#define NSTG  3
#define ST_A  (BM_ * BK_ * 2)  // 16384
#define ST_B  (BN_ * BK_ * 2)  // 32768
#define ST_BYTES (ST_A + ST_B) // 49152
#define SM0   1024
#define SMEM_TOTAL (SM0 + NSTG * ST_BYTES)   // 148480

// ---------------- scratch (static device globals) ----------------
__device__ __align__(128) __nv_bfloat16 g_Abf[(size_t)M_ * KS_];
__device__ __align__(128) __nv_bfloat16 g_Wbf[(size_t)V_ * KS_];
__device__ float g_G [(size_t)M_ * G4_];
__device__ float g_hb[B_ * G4_];
__device__ float g_dummy[2 * L_ * B_ * H_];

__device__ __forceinline__ float sigf(float x) { return 1.0f / (1.0f + expf(-x)); }

// ---------------- PTX helpers (base sm_90/sm_80 ISA only) ----------------
__device__ __forceinline__ uint32_t smem_u32(const void* p) {
    uint32_t a;
    asm("{ .reg .u64 t; cvta.to.shared.u64 t, %1; cvt.u32.u64 %0, t; }" : "=r"(a) : "l"(p));
    return a;
}
__device__ __forceinline__ void mbar_init(uint32_t a, uint32_t c) {
    asm volatile("mbarrier.init.shared.b64 [%0], %1;" :: "r"(a), "r"(c) : "memory");
}
__device__ __forceinline__ void mbar_expect_tx(uint32_t a, uint32_t b) {
    asm volatile("mbarrier.arrive.expect_tx.shared.b64 _, [%0], %1;" :: "r"(a), "r"(b) : "memory");
}
__device__ __forceinline__ void mbar_wait(uint32_t a, uint32_t ph) {
    asm volatile(
        "{ .reg .pred P;\n"
        "WL_%=: mbarrier.try_wait.parity.acquire.cta.shared::cta.b64 P, [%0], %1, 0x989680;\n"
        "@P bra.uni WD_%=;\n"
        "bra.uni WL_%=;\n"
        "WD_%=: }" :: "r"(a), "r"(ph) : "memory");
}
__device__ __forceinline__ void tma2d(uint32_t dst, const CUtensorMap* m, int x, int y, uint32_t mbar) {
    asm volatile(
        "cp.async.bulk.tensor.2d.shared::cta.global.tile.mbarrier::complete_tx::bytes "
        "[%0], [%1, {%2, %3}], [%4];"
        :: "r"(dst), "l"(m), "r"(x), "r"(y), "r"(mbar) : "memory");
}
__device__ __forceinline__ void ldsm4(uint32_t& r0, uint32_t& r1, uint32_t& r2, uint32_t& r3,
                                      uint32_t addr) {
    asm volatile("ldmatrix.sync.aligned.m8n8.x4.shared.b16 {%0,%1,%2,%3}, [%4];"
                 : "=r"(r0), "=r"(r1), "=r"(r2), "=r"(r3) : "r"(addr));
}
__device__ __forceinline__ void mma16816(float* c, const uint32_t* a, uint32_t b0, uint32_t b1) {
    asm volatile(
        "mma.sync.aligned.m16n8k16.row.col.f32.bf16.bf16.f32 "
        "{%0,%1,%2,%3}, {%4,%5,%6,%7}, {%8,%9}, {%0,%1,%2,%3};"
        : "+f"(c[0]), "+f"(c[1]), "+f"(c[2]), "+f"(c[3])
        : "r"(a[0]), "r"(a[1]), "r"(a[2]), "r"(a[3]), "r"(b0), "r"(b1));
}

// ---------------------------------------------------------------------------
// bf16 split-precision GEMM: C[m,n] = sum_k A'[m,k] * B'[n,k] (+bias)
// TMA SW128 loads, ldmatrix.x4 consumption, mma.sync.m16n8k16 compute.
// 256 threads = 8 warps (2m x 4n), warp tile 64x64, CTA tile 128x256, BK=64.
// grid: x = m-tile (fast -> B-tile L2 sharing), y = n-tile.
// ---------------------------------------------------------------------------
__global__ __launch_bounds__(256, 1)
void gemm_bf16(const __grid_constant__ CUtensorMap mapA,
               const __grid_constant__ CUtensorMap mapB,
               float* __restrict__ C, int ldc,
               const float* __restrict__ bias) {
    extern __shared__ __align__(1024) char smem[];
    const uint32_t sb = smem_u32(smem);
    const int tid = threadIdx.x, wid = tid >> 5, lane = tid & 31;
    const int m0 = blockIdx.x * BM_;
    const int n0 = blockIdx.y * BN_;
    const int wm = (wid & 1) * 64;        // warp m offset in CTA tile
    const int wn = (wid >> 1) * 64;       // warp n offset in CTA tile

    const uint32_t FULL = sb;             // 3 mbarriers, 8B each

    if (tid == 0) {
        #pragma unroll
        for (int s = 0; s < NSTG; ++s) mbar_init(FULL + 8 * s, 1);
    }
    __syncthreads();

    if (tid == 0) {
        #pragma unroll
        for (int s = 0; s < NSTG; ++s) {
            mbar_expect_tx(FULL + 8 * s, ST_BYTES);
            uint32_t sa = sb + SM0 + s * ST_BYTES;
            tma2d(sa,        &mapA, s * BK_, m0, FULL + 8 * s);
            tma2d(sa + ST_A, &mapB, s * BK_, n0, FULL + 8 * s);
        }
    }

    float c[4][8][4];
    #pragma unroll
    for (int mi = 0; mi < 4; ++mi)
        #pragma unroll
        for (int nj = 0; nj < 8; ++nj)
            #pragma unroll
            for (int q = 0; q < 4; ++q) c[mi][nj][q] = 0.f;

    const int lr = lane & 15;     // ldmatrix row within 16
    const int hi = lane >> 4;     // ldmatrix k-chunk select

    for (int kt = 0; kt < KT_; ++kt) {
        const int s = kt % NSTG;
        mbar_wait(FULL + 8 * s, (kt / NSTG) & 1);
        const uint32_t saA = sb + SM0 + s * ST_BYTES;
        const uint32_t saB = saA + ST_A;

        #pragma unroll
        for (int kk = 0; kk < 4; ++kk) {        // four k16 steps in BK=64
            uint32_t am[4][4], bt[4][4];
            #pragma unroll
            for (int mi = 0; mi < 4; ++mi) {
                int r = wm + mi * 16 + lr;
                uint32_t addr = saA + r * 128 + ((((kk << 1) | hi) ^ (r & 7)) << 4);
                ldsm4(am[mi][0], am[mi][1], am[mi][2], am[mi][3], addr);
            }
            #pragma unroll
            for (int nj = 0; nj < 4; ++nj) {
                int r = wn + nj * 16 + lr;
                uint32_t addr = saB + r * 128 + ((((kk << 1) | hi) ^ (r & 7)) << 4);
                ldsm4(bt[nj][0], bt[nj][1], bt[nj][2], bt[nj][3], addr);
            }
            #pragma unroll
            for (int mi = 0; mi < 4; ++mi)
                #pragma unroll
                for (int n8 = 0; n8 < 8; ++n8)
                    mma16816(c[mi][n8], am[mi],
                             bt[n8 >> 1][n8 & 1], bt[n8 >> 1][(n8 & 1) + 2]);
        }

        __syncthreads();   // all warps done with slot s
        if (tid == 0 && kt + NSTG < KT_) {
            mbar_expect_tx(FULL + 8 * s, ST_BYTES);
            uint32_t sa = sb + SM0 + s * ST_BYTES;
            tma2d(sa,        &mapA, (kt + NSTG) * BK_, m0, FULL + 8 * s);
            tma2d(sa + ST_A, &mapB, (kt + NSTG) * BK_, n0, FULL + 8 * s);
        }
    }

    // -------- epilogue: direct register -> global stores --------
    const int r4 = lane >> 2;            // accum row within 8
    const int c2 = (lane & 3) << 1;      // accum col pair
    #pragma unroll
    for (int mi = 0; mi < 4; ++mi) {
        int row0 = m0 + wm + mi * 16 + r4;
        #pragma unroll
        for (int n8 = 0; n8 < 8; ++n8) {
            int col = n0 + wn + n8 * 8 + c2;
            float bx = 0.f, by = 0.f;
            if (bias) { bx = bias[col]; by = bias[col + 1]; }
            float2 v0 = { c[mi][n8][0] + bx, c[mi][n8][1] + by };
            float2 v1 = { c[mi][n8][2] + bx, c[mi][n8][3] + by };
            *reinterpret_cast<float2*>(C + (size_t)row0 * ldc + col) = v0;
            *reinterpret_cast<float2*>(C + (size_t)(row0 + 8) * ldc + col) = v1;
        }
    }
}

// ---------------------------------------------------------------------------
// embed + relu + bf16 split into A' layout [M, 3*512] = [hi | hi | lo]
// ---------------------------------------------------------------------------
__global__ void embed_split_kernel(const int* __restrict__ tgt,
                                   const float* __restrict__ emb) {
    int idx = blockIdx.x * 256 + threadIdx.x;   // over M_*H_
    int m = idx >> 9, j = idx & 511;
    int b = m >> 7, t = m & 127;
    int tok = (t == 0) ? 1 : tgt[b * T_ + t - 1];
    float v = fmaxf(emb[(size_t)tok * H_ + j], 0.f);
    __nv_bfloat16 hi = __float2bfloat16(v);
    __nv_bfloat16 lo = __float2bfloat16(v - __bfloat162float(hi));
    size_t base = (size_t)m * KS_;
    g_Abf[base + j] = hi;
    g_Abf[base + H_ + j] = hi;
    g_Abf[base + 2 * H_ + j] = lo;
}

// ---------------------------------------------------------------------------
// weight split into B' layout [N, 3*512] = [hi | lo | hi]
// ---------------------------------------------------------------------------
__global__ void wsplit_kernel(const float* __restrict__ W, int total) {
    int idx = blockIdx.x * 256 + threadIdx.x;
    if (idx >= total) return;
    int row = idx >> 9, j = idx & 511;
    float v = W[idx];
    __nv_bfloat16 hi = __float2bfloat16(v);
    __nv_bfloat16 lo = __float2bfloat16(v - __bfloat162float(hi));
    size_t base = (size_t)row * KS_;
    g_Wbf[base + j] = hi;
    g_Wbf[base + H_ + j] = lo;
    g_Wbf[base + 2 * H_ + j] = hi;
}

// ---------------------------------------------------------------------------
// hb[b][g] = dot(h0[b,:], W_hh[g,:]) + b_ih[g] + b_hh[g]   (fp32, tiny)
// ---------------------------------------------------------------------------
__global__ void hb_kernel(const float* __restrict__ h0,
                          const float* __restrict__ Whh,
                          const float* __restrict__ bih,
                          const float* __restrict__ bhh) {
    int g = blockIdx.x * 8 + threadIdx.y;
    int b = blockIdx.y;
    const float4* hr = reinterpret_cast<const float4*>(h0 + (size_t)b * H_);
    const float4* wr = reinterpret_cast<const float4*>(Whh + (size_t)g * H_);
    float s = 0.f;
    for (int k = threadIdx.x; k < H_ / 4; k += 32) {
        float4 a = hr[k], w = wr[k];
        s += a.x * w.x + a.y * w.y + a.z * w.z + a.w * w.w;
    }
    #pragma unroll
    for (int o = 16; o; o >>= 1) s += __shfl_xor_sync(0xffffffffu, s, o);
    if (threadIdx.x == 0) g_hb[b * G4_ + g] = s + bih[g] + bhh[g];
}

// ---------------------------------------------------------------------------
// LSTM elementwise; writes h split back into A' layout + h_last/c_last
// ---------------------------------------------------------------------------
__global__ void lstm_split_kernel(const float* __restrict__ c0,
                                  float* __restrict__ out_h,
                                  float* __restrict__ out_c) {
    int idx = blockIdx.x * 256 + threadIdx.x;  // over M_*H_
    int m = idx >> 9, j = idx & 511;
    int b = m >> 7, t = m & 127;
    const float* gr  = g_G  + (size_t)m * G4_;
    const float* hbb = g_hb + (size_t)b * G4_;
    float iv = gr[j]          + hbb[j];
    float fv = gr[H_ + j]     + hbb[H_ + j];
    float gv = gr[2 * H_ + j] + hbb[2 * H_ + j];
    float ov = gr[3 * H_ + j] + hbb[3 * H_ + j];
    float c = sigf(fv) * c0[(size_t)b * H_ + j] + sigf(iv) * tanhf(gv);
    float h = sigf(ov) * tanhf(c);
    __nv_bfloat16 hi = __float2bfloat16(h);
    __nv_bfloat16 lo = __float2bfloat16(h - __bfloat162float(hi));
    size_t base = (size_t)m * KS_;
    g_Abf[base + j] = hi;
    g_Abf[base + H_ + j] = hi;
    g_Abf[base + 2 * H_ + j] = lo;
    if (t == T_ - 1) {
        out_h[(size_t)b * H_ + j] = h;
        out_c[(size_t)b * H_ + j] = c;
    }
}

// ---------------------------------------------------------------------------
typedef CUresult (*PFN_tmapEnc)(CUtensorMap*, CUtensorMapDataType, unsigned int, void*,
                                const unsigned long long*, const unsigned long long*,
                                const unsigned int*, const unsigned int*,
                                CUtensorMapInterleave, CUtensorMapSwizzle,
                                CUtensorMapL2promotion, CUtensorMapFloatOOBfill);

extern "C" void kernel_launch(void* const* d_in, const int* in_sizes, int n_in,
                              void* d_out, int out_size) {
    const float* enc_h = (const float*)d_in[1];
    const float* enc_c = (const float*)d_in[2];
    const int*   tgt   = (const int*)  d_in[3];
    const float* emb   = (const float*)d_in[4];
    const float* W_ih  = (const float*)d_in[5];
    const float* W_hh  = (const float*)d_in[6];
    const float* b_ih  = (const float*)d_in[7];
    const float* b_hh  = (const float*)d_in[8];
    const float* W_out = (const float*)d_in[9];
    const float* b_out = (const float*)d_in[10];
    float* out = (float*)d_out;

    static bool inited = false;
    static float* Gp = nullptr;
    static float* dummy = nullptr;
    static CUtensorMap mapA, mapB;
    if (!inited) {
        void* p;
        cudaGetSymbolAddress(&p, g_G);     Gp    = (float*)p;
        cudaGetSymbolAddress(&p, g_dummy); dummy = (float*)p;
        void* pAbf; cudaGetSymbolAddress(&pAbf, g_Abf);
        void* pWbf; cudaGetSymbolAddress(&pWbf, g_Wbf);

        void* fn = nullptr;
        cudaDriverEntryPointQueryResult qr;
        cudaGetDriverEntryPoint("cuTensorMapEncodeTiled", &fn, cudaEnableDefault, &qr);
        PFN_tmapEnc enc = (PFN_tmapEnc)fn;

        unsigned long long dimsA[2] = { (unsigned long long)KS_, (unsigned long long)M_ };
        unsigned long long strA[1]  = { (unsigned long long)KS_ * 2 };
        unsigned int boxA[2] = { (unsigned int)BK_, (unsigned int)BM_ };
        unsigned int es[2]   = { 1u, 1u };
        enc(&mapA, CU_TENSOR_MAP_DATA_TYPE_BFLOAT16, 2, pAbf, dimsA, strA, boxA, es,
            CU_TENSOR_MAP_INTERLEAVE_NONE, CU_TENSOR_MAP_SWIZZLE_128B,
            CU_TENSOR_MAP_L2_PROMOTION_L2_128B, CU_TENSOR_MAP_FLOAT_OOB_FILL_NONE);
        unsigned long long dimsB[2] = { (unsigned long long)KS_, (unsigned long long)V_ };
        unsigned int boxB[2] = { (unsigned int)BK_, (unsigned int)BN_ };
        enc(&mapB, CU_TENSOR_MAP_DATA_TYPE_BFLOAT16, 2, pWbf, dimsB, strA, boxB, es,
            CU_TENSOR_MAP_INTERLEAVE_NONE, CU_TENSOR_MAP_SWIZZLE_128B,
            CU_TENSOR_MAP_L2_PROMOTION_L2_128B, CU_TENSOR_MAP_FLOAT_OOB_FILL_NONE);

        cudaFuncSetAttribute(gemm_bf16, cudaFuncAttributeMaxDynamicSharedMemorySize, SMEM_TOTAL);
        inited = true;
    }

    // output layout: [logits (M_*V_), h_last (L,B,H), c_last (L,B,H)]
    const long long need = (long long)M_ * V_ + 2LL * L_ * B_ * H_;
    float *hl, *cl;
    if ((long long)out_size >= need) {
        hl = out + (size_t)M_ * V_;
        cl = hl + (size_t)L_ * B_ * H_;
    } else {
        hl = dummy;
        cl = dummy + (size_t)L_ * B_ * H_;
    }

    // 1. embedding + relu + split
    embed_split_kernel<<<(M_ * H_) / 256, 256>>>(tgt, emb);

    // 2. two independent single-step LSTM layers
    for (int l = 0; l < L_; ++l) {
        hb_kernel<<<dim3(G4_ / 8, B_), dim3(32, 8)>>>(
            enc_h + (size_t)l * B_ * H_, W_hh + (size_t)l * G4_ * H_,
            b_ih + (size_t)l * G4_, b_hh + (size_t)l * G4_);
        wsplit_kernel<<<(G4_ * H_) / 256, 256>>>(W_ih + (size_t)l * G4_ * H_, G4_ * H_);
        gemm_bf16<<<dim3(M_ / BM_, G4_ / BN_), 256, SMEM_TOTAL>>>(
            mapA, mapB, Gp, G4_, nullptr);
        lstm_split_kernel<<<(M_ * H_) / 256, 256>>>(
            enc_c + (size_t)l * B_ * H_,
            hl + (size_t)l * B_ * H_, cl + (size_t)l * B_ * H_);
    }

    // 3. output projection: logits = X2' * W_out'^T + b_out
    wsplit_kernel<<<(V_ * H_) / 256, 256>>>(W_out, V_ * H_);
    gemm_bf16<<<dim3(M_ / BM_, V_ / BN_), 256, SMEM_TOTAL>>>(
        mapA, mapB, out, V_, b_out);
}

// round 4
// speedup vs baseline: 5.7267x; 2.2894x over previous
#include <cuda_runtime.h>
#include <cuda_fp16.h>
#include <cuda.h>
#include <cstdint>

// ---------------- problem constants ----------------
#define B_    16
#define T_    128
#define H_    512
#define L_    2
#define V_    32000
#define M_    (B_ * T_)        // 2048
#define G4_   (4 * H_)         // 2048

// ---------------- GEMM tiling ----------------
#define BM_   128
#define BN_   256
#define BK_   64               // fp16 = 128 bytes/row = SW128 atom
#define KT_   (H_ / BK_)       // 8 k-tiles
#define NSTG  3
#define ST_A  (BM_ * BK_ * 2)  // 16384
#define ST_B  (BN_ * BK_ * 2)  // 32768
#define ST_BYTES (ST_A + ST_B) // 49152
#define SM0   1024
#define SMEM_TOTAL (SM0 + NSTG * ST_BYTES)   // 148480

// ---------------- scratch (static device globals) ----------------
__device__ __align__(128) __half g_Ahf[(size_t)M_ * H_];
__device__ __align__(128) __half g_Whf[(size_t)V_ * H_];
__device__ float g_G [(size_t)M_ * G4_];
__device__ float g_hb[B_ * G4_];
__device__ float g_dummy[2 * L_ * B_ * H_];

__device__ __forceinline__ float sigf(float x) { return 1.0f / (1.0f + expf(-x)); }

// ---------------- PTX helpers (base ISA only; no tcgen05 on sm_103 target) ----
__device__ __forceinline__ uint32_t smem_u32(const void* p) {
    uint32_t a;
    asm("{ .reg .u64 t; cvta.to.shared.u64 t, %1; cvt.u32.u64 %0, t; }" : "=r"(a) : "l"(p));
    return a;
}
__device__ __forceinline__ void mbar_init(uint32_t a, uint32_t c) {
    asm volatile("mbarrier.init.shared.b64 [%0], %1;" :: "r"(a), "r"(c) : "memory");
}
__device__ __forceinline__ void mbar_expect_tx(uint32_t a, uint32_t b) {
    asm volatile("mbarrier.arrive.expect_tx.shared.b64 _, [%0], %1;" :: "r"(a), "r"(b) : "memory");
}
__device__ __forceinline__ void mbar_wait(uint32_t a, uint32_t ph) {
    asm volatile(
        "{ .reg .pred P;\n"
        "WL_%=: mbarrier.try_wait.parity.acquire.cta.shared::cta.b64 P, [%0], %1, 0x989680;\n"
        "@P bra.uni WD_%=;\n"
        "bra.uni WL_%=;\n"
        "WD_%=: }" :: "r"(a), "r"(ph) : "memory");
}
__device__ __forceinline__ void tma2d(uint32_t dst, const CUtensorMap* m, int x, int y, uint32_t mbar) {
    asm volatile(
        "cp.async.bulk.tensor.2d.shared::cta.global.tile.mbarrier::complete_tx::bytes "
        "[%0], [%1, {%2, %3}], [%4];"
        :: "r"(dst), "l"(m), "r"(x), "r"(y), "r"(mbar) : "memory");
}
__device__ __forceinline__ void ldsm4(uint32_t& r0, uint32_t& r1, uint32_t& r2, uint32_t& r3,
                                      uint32_t addr) {
    asm volatile("ldmatrix.sync.aligned.m8n8.x4.shared.b16 {%0,%1,%2,%3}, [%4];"
                 : "=r"(r0), "=r"(r1), "=r"(r2), "=r"(r3) : "r"(addr));
}
__device__ __forceinline__ void mma16816(float* c, const uint32_t* a, uint32_t b0, uint32_t b1) {
    asm volatile(
        "mma.sync.aligned.m16n8k16.row.col.f32.f16.f16.f32 "
        "{%0,%1,%2,%3}, {%4,%5,%6,%7}, {%8,%9}, {%0,%1,%2,%3};"
        : "+f"(c[0]), "+f"(c[1]), "+f"(c[2]), "+f"(c[3])
        : "r"(a[0]), "r"(a[1]), "r"(a[2]), "r"(a[3]), "r"(b0), "r"(b1));
}

// ---------------------------------------------------------------------------
// fp16 GEMM: C[m,n] = sum_k A[m,k] * B[n,k] (+bias), fp32 accumulate.
// TMA SW128 loads, ldmatrix.x4 consumption, mma.sync.m16n8k16 compute.
// 256 threads = 8 warps (2m x 4n), warp tile 64x64, CTA tile 128x256, BK=64.
// grid: x = m-tile (fast -> B-tile L2 sharing), y = n-tile.
// ---------------------------------------------------------------------------
__global__ __launch_bounds__(256, 1)
void gemm_f16(const __grid_constant__ CUtensorMap mapA,
              const __grid_constant__ CUtensorMap mapB,
              float* __restrict__ C, int ldc,
              const float* __restrict__ bias) {
    extern __shared__ __align__(1024) char smem[];
    const uint32_t sb = smem_u32(smem);
    const int tid = threadIdx.x, wid = tid >> 5, lane = tid & 31;
    const int m0 = blockIdx.x * BM_;
    const int n0 = blockIdx.y * BN_;
    const int wm = (wid & 1) * 64;        // warp m offset in CTA tile
    const int wn = (wid >> 1) * 64;       // warp n offset in CTA tile

    const uint32_t FULL = sb;             // NSTG mbarriers, 8B each

    if (tid == 0) {
        #pragma unroll
        for (int s = 0; s < NSTG; ++s) mbar_init(FULL + 8 * s, 1);
    }
    __syncthreads();

    if (tid == 0) {
        #pragma unroll
        for (int s = 0; s < NSTG; ++s) {
            mbar_expect_tx(FULL + 8 * s, ST_BYTES);
            uint32_t sa = sb + SM0 + s * ST_BYTES;
            tma2d(sa,        &mapA, s * BK_, m0, FULL + 8 * s);
            tma2d(sa + ST_A, &mapB, s * BK_, n0, FULL + 8 * s);
        }
    }

    float c[4][8][4];
    #pragma unroll
    for (int mi = 0; mi < 4; ++mi)
        #pragma unroll
        for (int nj = 0; nj < 8; ++nj)
            #pragma unroll
            for (int q = 0; q < 4; ++q) c[mi][nj][q] = 0.f;

    const int lr = lane & 15;     // ldmatrix row within 16
    const int hi = lane >> 4;     // ldmatrix k-chunk select

    // hoisted swizzled ldmatrix offsets (kk enters as a pure XOR of bits 5..6)
    uint32_t offA[4], offB[4];
    #pragma unroll
    for (int mi = 0; mi < 4; ++mi) {
        int r = wm + mi * 16 + lr;
        offA[mi] = (uint32_t)(r * 128 + ((hi ^ (r & 7)) << 4));
    }
    #pragma unroll
    for (int nj = 0; nj < 4; ++nj) {
        int r = wn + nj * 16 + lr;
        offB[nj] = (uint32_t)(ST_A + r * 128 + ((hi ^ (r & 7)) << 4));
    }

    for (int kt = 0; kt < KT_; ++kt) {
        const int s = kt % NSTG;
        mbar_wait(FULL + 8 * s, (kt / NSTG) & 1);
        const uint32_t sa = sb + SM0 + s * ST_BYTES;   // 1024-aligned; XOR below is carry-free

        #pragma unroll
        for (int kk = 0; kk < 4; ++kk) {        // four k16 steps in BK=64
            const uint32_t kx = (uint32_t)(kk << 5);
            uint32_t am[4][4], bt[4][4];
            #pragma unroll
            for (int mi = 0; mi < 4; ++mi)
                ldsm4(am[mi][0], am[mi][1], am[mi][2], am[mi][3], sa + (offA[mi] ^ kx));
            #pragma unroll
            for (int nj = 0; nj < 4; ++nj)
                ldsm4(bt[nj][0], bt[nj][1], bt[nj][2], bt[nj][3], sa + (offB[nj] ^ kx));
            #pragma unroll
            for (int mi = 0; mi < 4; ++mi)
                #pragma unroll
                for (int n8 = 0; n8 < 8; ++n8)
                    mma16816(c[mi][n8], am[mi],
                             bt[n8 >> 1][n8 & 1], bt[n8 >> 1][(n8 & 1) + 2]);
        }

        __syncthreads();   // all warps done with slot s
        if (tid == 0 && kt + NSTG < KT_) {
            mbar_expect_tx(FULL + 8 * s, ST_BYTES);
            uint32_t sn = sb + SM0 + s * ST_BYTES;
            tma2d(sn,        &mapA, (kt + NSTG) * BK_, m0, FULL + 8 * s);
            tma2d(sn + ST_A, &mapB, (kt + NSTG) * BK_, n0, FULL + 8 * s);
        }
    }

    // -------- epilogue: direct register -> global stores --------
    const int r4 = lane >> 2;            // accum row within 8
    const int c2 = (lane & 3) << 1;      // accum col pair
    #pragma unroll
    for (int mi = 0; mi < 4; ++mi) {
        int row0 = m0 + wm + mi * 16 + r4;
        #pragma unroll
        for (int n8 = 0; n8 < 8; ++n8) {
            int col = n0 + wn + n8 * 8 + c2;
            float bx = 0.f, by = 0.f;
            if (bias) { bx = bias[col]; by = bias[col + 1]; }
            float2 v0 = { c[mi][n8][0] + bx, c[mi][n8][1] + by };
            float2 v1 = { c[mi][n8][2] + bx, c[mi][n8][3] + by };
            *reinterpret_cast<float2*>(C + (size_t)row0 * ldc + col) = v0;
            *reinterpret_cast<float2*>(C + (size_t)(row0 + 8) * ldc + col) = v1;
        }
    }
}

// ---------------------------------------------------------------------------
// embed + relu -> fp16 A [M, H]
// ---------------------------------------------------------------------------
__global__ void embed_half_kernel(const int* __restrict__ tgt,
                                  const float* __restrict__ emb) {
    int idx = blockIdx.x * 256 + threadIdx.x;   // over M_*H_/4
    int m = idx >> 7;          // H_/4 = 128 float4 per row
    int q = idx & 127;
    int b = m >> 7, t = m & 127;
    int tok = (t == 0) ? 1 : tgt[b * T_ + t - 1];
    float4 v = reinterpret_cast<const float4*>(emb + (size_t)tok * H_)[q];
    __half2* dst = reinterpret_cast<__half2*>(g_Ahf) + idx * 2;
    dst[0] = __floats2half2_rn(fmaxf(v.x, 0.f), fmaxf(v.y, 0.f));
    dst[1] = __floats2half2_rn(fmaxf(v.z, 0.f), fmaxf(v.w, 0.f));
}

// ---------------------------------------------------------------------------
// weight fp32 -> fp16 (layout identical, pure convert)
// ---------------------------------------------------------------------------
__global__ void wconv_kernel(const float* __restrict__ W, int total4) {
    int idx = blockIdx.x * 256 + threadIdx.x;
    if (idx >= total4) return;
    float4 v = reinterpret_cast<const float4*>(W)[idx];
    __half2* dst = reinterpret_cast<__half2*>(g_Whf) + idx * 2;
    dst[0] = __floats2half2_rn(v.x, v.y);
    dst[1] = __floats2half2_rn(v.z, v.w);
}

// ---------------------------------------------------------------------------
// hb[b][g] = dot(h0[b,:], W_hh[g,:]) + b_ih[g] + b_hh[g]   (fp32, tiny)
// ---------------------------------------------------------------------------
__global__ void hb_kernel(const float* __restrict__ h0,
                          const float* __restrict__ Whh,
                          const float* __restrict__ bih,
                          const float* __restrict__ bhh) {
    int g = blockIdx.x * 8 + threadIdx.y;
    int b = blockIdx.y;
    const float4* hr = reinterpret_cast<const float4*>(h0 + (size_t)b * H_);
    const float4* wr = reinterpret_cast<const float4*>(Whh + (size_t)g * H_);
    float s = 0.f;
    for (int k = threadIdx.x; k < H_ / 4; k += 32) {
        float4 a = hr[k], w = wr[k];
        s += a.x * w.x + a.y * w.y + a.z * w.z + a.w * w.w;
    }
    #pragma unroll
    for (int o = 16; o; o >>= 1) s += __shfl_xor_sync(0xffffffffu, s, o);
    if (threadIdx.x == 0) g_hb[b * G4_ + g] = s + bih[g] + bhh[g];
}

// ---------------------------------------------------------------------------
// LSTM elementwise; writes h (fp16) back to A + h_last/c_last (fp32)
// ---------------------------------------------------------------------------
__global__ void lstm_half_kernel(const float* __restrict__ c0,
                                 float* __restrict__ out_h,
                                 float* __restrict__ out_c) {
    int idx = blockIdx.x * 256 + threadIdx.x;  // over M_*H_
    int m = idx >> 9, j = idx & 511;
    int b = m >> 7, t = m & 127;
    const float* gr  = g_G  + (size_t)m * G4_;
    const float* hbb = g_hb + (size_t)b * G4_;
    float iv = gr[j]          + hbb[j];
    float fv = gr[H_ + j]     + hbb[H_ + j];
    float gv = gr[2 * H_ + j] + hbb[2 * H_ + j];
    float ov = gr[3 * H_ + j] + hbb[3 * H_ + j];
    float c = sigf(fv) * c0[(size_t)b * H_ + j] + sigf(iv) * tanhf(gv);
    float h = sigf(ov) * tanhf(c);
    g_Ahf[(size_t)m * H_ + j] = __float2half(h);
    if (t == T_ - 1) {
        out_h[(size_t)b * H_ + j] = h;
        out_c[(size_t)b * H_ + j] = c;
    }
}

// ---------------------------------------------------------------------------
typedef CUresult (*PFN_tmapEnc)(CUtensorMap*, CUtensorMapDataType, unsigned int, void*,
                                const unsigned long long*, const unsigned long long*,
                                const unsigned int*, const unsigned int*,
                                CUtensorMapInterleave, CUtensorMapSwizzle,
                                CUtensorMapL2promotion, CUtensorMapFloatOOBfill);

extern "C" void kernel_launch(void* const* d_in, const int* in_sizes, int n_in,
                              void* d_out, int out_size) {
    const float* enc_h = (const float*)d_in[1];
    const float* enc_c = (const float*)d_in[2];
    const int*   tgt   = (const int*)  d_in[3];
    const float* emb   = (const float*)d_in[4];
    const float* W_ih  = (const float*)d_in[5];
    const float* W_hh  = (const float*)d_in[6];
    const float* b_ih  = (const float*)d_in[7];
    const float* b_hh  = (const float*)d_in[8];
    const float* W_out = (const float*)d_in[9];
    const float* b_out = (const float*)d_in[10];
    float* out = (float*)d_out;

    static bool inited = false;
    static float* Gp = nullptr;
    static float* dummy = nullptr;
    static CUtensorMap mapA, mapB;
    if (!inited) {
        void* p;
        cudaGetSymbolAddress(&p, g_G);     Gp    = (float*)p;
        cudaGetSymbolAddress(&p, g_dummy); dummy = (float*)p;
        void* pA; cudaGetSymbolAddress(&pA, g_Ahf);
        void* pW; cudaGetSymbolAddress(&pW, g_Whf);

        void* fn = nullptr;
        cudaDriverEntryPointQueryResult qr;
        cudaGetDriverEntryPoint("cuTensorMapEncodeTiled", &fn, cudaEnableDefault, &qr);
        PFN_tmapEnc enc = (PFN_tmapEnc)fn;

        unsigned long long dimsA[2] = { (unsigned long long)H_, (unsigned long long)M_ };
        unsigned long long strA[1]  = { (unsigned long long)H_ * 2 };
        unsigned int boxA[2] = { (unsigned int)BK_, (unsigned int)BM_ };
        unsigned int es[2]   = { 1u, 1u };
        enc(&mapA, CU_TENSOR_MAP_DATA_TYPE_FLOAT16, 2, pA, dimsA, strA, boxA, es,
            CU_TENSOR_MAP_INTERLEAVE_NONE, CU_TENSOR_MAP_SWIZZLE_128B,
            CU_TENSOR_MAP_L2_PROMOTION_L2_128B, CU_TENSOR_MAP_FLOAT_OOB_FILL_NONE);
        unsigned long long dimsB[2] = { (unsigned long long)H_, (unsigned long long)V_ };
        unsigned int boxB[2] = { (unsigned int)BK_, (unsigned int)BN_ };
        enc(&mapB, CU_TENSOR_MAP_DATA_TYPE_FLOAT16, 2, pW, dimsB, strA, boxB, es,
            CU_TENSOR_MAP_INTERLEAVE_NONE, CU_TENSOR_MAP_SWIZZLE_128B,
            CU_TENSOR_MAP_L2_PROMOTION_L2_128B, CU_TENSOR_MAP_FLOAT_OOB_FILL_NONE);

        cudaFuncSetAttribute(gemm_f16, cudaFuncAttributeMaxDynamicSharedMemorySize, SMEM_TOTAL);
        inited = true;
    }

    // output layout: [logits (M_*V_), h_last (L,B,H), c_last (L,B,H)]
    const long long need = (long long)M_ * V_ + 2LL * L_ * B_ * H_;
    float *hl, *cl;
    if ((long long)out_size >= need) {
        hl = out + (size_t)M_ * V_;
        cl = hl + (size_t)L_ * B_ * H_;
    } else {
        hl = dummy;
        cl = dummy + (size_t)L_ * B_ * H_;
    }

    // 1. embedding + relu (fp16 A)
    embed_half_kernel<<<(M_ * H_ / 4) / 256, 256>>>(tgt, emb);

    // 2. two independent single-step LSTM layers
    for (int l = 0; l < L_; ++l) {
        hb_kernel<<<dim3(G4_ / 8, B_), dim3(32, 8)>>>(
            enc_h + (size_t)l * B_ * H_, W_hh + (size_t)l * G4_ * H_,
            b_ih + (size_t)l * G4_, b_hh + (size_t)l * G4_);
        wconv_kernel<<<((G4_ * H_ / 4) + 255) / 256, 256>>>(
            W_ih + (size_t)l * G4_ * H_, G4_ * H_ / 4);
        gemm_f16<<<dim3(M_ / BM_, G4_ / BN_), 256, SMEM_TOTAL>>>(
            mapA, mapB, Gp, G4_, nullptr);
        lstm_half_kernel<<<(M_ * H_) / 256, 256>>>(
            enc_c + (size_t)l * B_ * H_,
            hl + (size_t)l * B_ * H_, cl + (size_t)l * B_ * H_);
    }

    // 3. output projection: logits = X2 * W_out^T + b_out
    wconv_kernel<<<((V_ * H_ / 4) + 255) / 256, 256>>>(W_out, V_ * H_ / 4);
    gemm_f16<<<dim3(M_ / BM_, V_ / BN_), 256, SMEM_TOTAL>>>(
        mapA, mapB, out, V_, b_out);
}